// round 2
// baseline (speedup 1.0000x reference)
#include <cuda_runtime.h>
#include <cstdint>

// Problem constants
#define B_DIM 128
#define G_DIM 20000
#define N_ELEM (B_DIM * G_DIM)   // 2,560,000 (divisible by 256)
#define HID 64
#define NBM1 9                   // NUM_BINS - 1
#define NBINS 10
#define NSEG (HID + 1)           // 65 piecewise-linear segments
#define BLK 256
#define NBLK (N_ELEM / BLK)      // 10,000

// __device__ global scratch (no allocations allowed)
__device__ float  g_T[HID];              // sorted thresholds (+inf padded)
__device__ float2 g_AC[NSEG * NBM1];     // per (segment, bin): logit = A*x + C

// ---------------------------------------------------------------------------
// Setup: build the piecewise-linear table.
// logit_k(x) = b2[k] + sum_h W2[h,k] * leaky(x*w1[h] + b1[h])
// leaky slope pattern changes only at thr_h = -b1[h]/w1[h]. For segment j
// (between sorted thresholds T[j-1] and T[j]):
//   w1>0 : t_h >= 0  <=>  rank(thr_h) < j
//   w1<0 : t_h >= 0  <=>  rank(thr_h) >= j
//   w1==0: t_h >= 0  <=>  b1 >= 0      (thr set to +inf, excluded from search)
// ---------------------------------------------------------------------------
__global__ void setup_kernel(const float* __restrict__ W1,
                             const float* __restrict__ b1,
                             const float* __restrict__ W2,
                             const float* __restrict__ b2) {
    __shared__ float s_thr[HID];
    __shared__ int   s_idx[HID];
    __shared__ float s_w1[HID];
    __shared__ float s_b1[HID];

    int t = threadIdx.x;
    if (t < HID) {
        float w = W1[t];
        float b = b1[t];
        s_w1[t] = w;
        s_b1[t] = b;
        s_thr[t] = (w != 0.0f) ? (-b / w) : __int_as_float(0x7f800000); // +inf
    }
    __syncthreads();

    if (t < HID) {
        float thr = s_thr[t];
        int idx = 0;
        #pragma unroll
        for (int h = 0; h < HID; h++) {
            float o = s_thr[h];
            // stable rank (tie-break by index) -> permutation
            if (o < thr || (o == thr && h < t)) idx++;
        }
        s_idx[t] = idx;
        g_T[idx] = thr;
    }
    __syncthreads();

    if (t < NSEG * NBM1) {
        int j = t / NBM1;
        int k = t % NBM1;
        float A = 0.0f, C = 0.0f;
        #pragma unroll
        for (int h = 0; h < HID; h++) {
            float w = s_w1[h];
            float b = s_b1[h];
            bool pos;
            if (w > 0.0f)      pos = (s_idx[h] < j);
            else if (w < 0.0f) pos = (s_idx[h] >= j);
            else               pos = (b >= 0.0f);
            float scale = pos ? 1.0f : 0.01f;
            float w2s = W2[h * NBM1 + k] * scale;
            A = fmaf(w2s, w, A);
            C = fmaf(w2s, b, C);
        }
        g_AC[t] = make_float2(A, C + b2[k]);
    }
}

// ---------------------------------------------------------------------------
// Main: per element, binary-search segment, 9 FMA logits, softmax,
// smem-staged coalesced float4 output.
// ---------------------------------------------------------------------------
__global__ void __launch_bounds__(BLK)
expr_quantizer_kernel(const float* __restrict__ expr,
                      float* __restrict__ probs,
                      float* __restrict__ mask) {
    // 16B alignment is load-bearing: flushed with LDS.128/STG.128
    __shared__ __align__(16) float sOut[BLK * NBINS];  // 10 KB staging
    __shared__ float  sT[HID];
    __shared__ float2 sAC[NSEG * NBM1];

    int t = threadIdx.x;
    if (t < HID) sT[t] = g_T[t];
    for (int i = t; i < NSEG * NBM1; i += BLK) sAC[i] = g_AC[i];
    __syncthreads();

    int e = blockIdx.x * BLK + t;
    float x = expr[e];

    float out[NBINS];
    if (x != 0.0f) {
        mask[e] = 1.0f;
        // j = count of sorted thresholds <= x, in [0, 64]
        int j = 0;
        #pragma unroll
        for (int step = 64; step > 0; step >>= 1) {
            int nj = j + step;
            if (nj <= HID && sT[nj - 1] <= x) j = nj;
        }
        const float2* row = &sAC[j * NBM1];
        float lg[NBM1];
        float mx = -3.402823e38f;
        #pragma unroll
        for (int k = 0; k < NBM1; k++) {
            float2 ac = row[k];
            lg[k] = fmaf(ac.x, x, ac.y);
            mx = fmaxf(mx, lg[k]);
        }
        float sum = 0.0f;
        #pragma unroll
        for (int k = 0; k < NBM1; k++) {
            lg[k] = __expf(lg[k] - mx);
            sum += lg[k];
        }
        float inv = 1.0f / sum;
        out[0] = 0.0f;
        #pragma unroll
        for (int k = 0; k < NBM1; k++) out[k + 1] = lg[k] * inv;
    } else {
        mask[e] = 0.0f;
        out[0] = 1.0f;
        #pragma unroll
        for (int k = 1; k < NBINS; k++) out[k] = 0.0f;
    }

    #pragma unroll
    for (int k = 0; k < NBINS; k++) sOut[t * NBINS + k] = out[k];
    __syncthreads();

    // Coalesced flush: 2560 floats = 640 float4 per block; base is 16B-aligned
    float4* dst = reinterpret_cast<float4*>(probs + (size_t)blockIdx.x * (BLK * NBINS));
    const float4* src = reinterpret_cast<const float4*>(sOut);
    #pragma unroll
    for (int i = 0; i < 3; i++) {
        int idx = t + BLK * i;
        if (idx < (BLK * NBINS) / 4) dst[idx] = src[idx];
    }
}

extern "C" void kernel_launch(void* const* d_in, const int* in_sizes, int n_in,
                              void* d_out, int out_size) {
    const float* expr = (const float*)d_in[0];
    const float* W1   = (const float*)d_in[1];
    const float* b1   = (const float*)d_in[2];
    const float* W2   = (const float*)d_in[3];
    const float* b2   = (const float*)d_in[4];

    float* probs = (float*)d_out;
    float* mask  = (float*)d_out + (size_t)N_ELEM * NBINS;

    setup_kernel<<<1, NSEG * NBM1>>>(W1, b1, W2, b2);   // 585 threads >= 64
    expr_quantizer_kernel<<<NBLK, BLK>>>(expr, probs, mask);
}

// round 6
// speedup vs baseline: 1.0342x; 1.0342x over previous
#include <cuda_runtime.h>
#include <cstdint>

// Problem constants
#define B_DIM 128
#define G_DIM 20000
#define N_ELEM (B_DIM * G_DIM)   // 2,560,000 (divisible by 256)
#define HID 64
#define NBM1 9                   // NUM_BINS - 1
#define NBINS 10
#define NSEG (HID + 1)           // 65 piecewise-linear segments
#define ROWF 20                  // floats per table row (A0..A8,C0..C8,pad,pad) = 80B
#define BLK 256
#define NBLK (N_ELEM / BLK)      // 10,000
#define LOG2E 1.4426950408889634f

// __device__ global scratch (no allocations allowed)
__device__ float g_T[HID];                 // sorted thresholds (+inf padded)
__device__ __align__(16) float g_tab[NSEG * ROWF];  // log2-domain (A', C') table

// ---------------------------------------------------------------------------
// Setup: build the piecewise-linear table (in log2 domain).
// logit_k(x) = b2[k] + sum_h W2[h,k] * leaky(x*w1[h] + b1[h])
// Leaky slope pattern changes only at thr_h = -b1[h]/w1[h]. For segment j
// (x between sorted thresholds T[j-1] and T[j]):
//   w1>0 : pre-act >= 0  <=>  rank(thr_h) < j
//   w1<0 : pre-act >= 0  <=>  rank(thr_h) >= j
//   w1==0: pre-act >= 0  <=>  b1 >= 0     (thr = +inf, excluded from search)
// Stored scaled by log2(e) so the main kernel can use bare exp2f.
// ---------------------------------------------------------------------------
__global__ void setup_kernel(const float* __restrict__ W1,
                             const float* __restrict__ b1,
                             const float* __restrict__ W2,
                             const float* __restrict__ b2) {
    __shared__ float s_thr[HID];
    __shared__ int   s_idx[HID];
    __shared__ float s_w1[HID];
    __shared__ float s_b1[HID];

    int t = threadIdx.x;
    if (t < HID) {
        float w = W1[t];
        float b = b1[t];
        s_w1[t] = w;
        s_b1[t] = b;
        s_thr[t] = (w != 0.0f) ? (-b / w) : __int_as_float(0x7f800000); // +inf
    }
    __syncthreads();

    if (t < HID) {
        float thr = s_thr[t];
        int idx = 0;
        #pragma unroll
        for (int h = 0; h < HID; h++) {
            float o = s_thr[h];
            if (o < thr || (o == thr && h < t)) idx++;  // stable rank
        }
        s_idx[t] = idx;
        g_T[idx] = thr;
    }
    __syncthreads();

    if (t < NSEG * NBM1) {
        int j = t / NBM1;
        int k = t % NBM1;
        float A = 0.0f, C = 0.0f;
        #pragma unroll
        for (int h = 0; h < HID; h++) {
            float w = s_w1[h];
            float b = s_b1[h];
            bool pos;
            if (w > 0.0f)      pos = (s_idx[h] < j);
            else if (w < 0.0f) pos = (s_idx[h] >= j);
            else               pos = (b >= 0.0f);
            float scale = pos ? 1.0f : 0.01f;
            float w2s = W2[h * NBM1 + k] * scale;
            A = fmaf(w2s, w, A);
            C = fmaf(w2s, b, C);
        }
        g_tab[j * ROWF + k]        = A * LOG2E;
        g_tab[j * ROWF + NBM1 + k] = (C + b2[k]) * LOG2E;
    }
    // zero the row padding
    if (t < NSEG) {
        g_tab[t * ROWF + 18] = 0.0f;
        g_tab[t * ROWF + 19] = 0.0f;
    }
}

// ---------------------------------------------------------------------------
// Main: per element, binary-search segment, vectorized row fetch (5 LDS.128),
// base-2 softmax, smem-staged coalesced float4 output.
// ---------------------------------------------------------------------------
__global__ void __launch_bounds__(BLK)
expr_quantizer_kernel(const float* __restrict__ expr,
                      float* __restrict__ probs,
                      float* __restrict__ mask) {
    __shared__ __align__(16) float sOut[BLK * NBINS];     // 10 KB staging
    __shared__ __align__(16) float sTab[NSEG * ROWF];     // 5.2 KB table
    __shared__ float sT[HID];

    int t = threadIdx.x;
    if (t < HID) sT[t] = g_T[t];
    {
        const float4* gsrc = reinterpret_cast<const float4*>(g_tab);
        float4* sdst = reinterpret_cast<float4*>(sTab);
        for (int i = t; i < (NSEG * ROWF) / 4; i += BLK) sdst[i] = gsrc[i];
    }
    __syncthreads();

    int e = blockIdx.x * BLK + t;
    float x = expr[e];

    float out[NBINS];
    if (x != 0.0f) {
        mask[e] = 1.0f;
        // j = count of sorted thresholds <= x, in [0, 64]
        int j = 0;
        #pragma unroll
        for (int step = 64; step > 0; step >>= 1) {
            int nj = j + step;
            if (nj <= HID && sT[nj - 1] <= x) j = nj;
        }
        const float4* row = reinterpret_cast<const float4*>(&sTab[j * ROWF]);
        float4 r0 = row[0];  // A0..A3
        float4 r1 = row[1];  // A4..A7
        float4 r2 = row[2];  // A8, C0, C1, C2
        float4 r3 = row[3];  // C3..C6
        float4 r4 = row[4];  // C7, C8, pad, pad

        float l0 = fmaf(r0.x, x, r2.y);
        float l1 = fmaf(r0.y, x, r2.z);
        float l2 = fmaf(r0.z, x, r2.w);
        float l3 = fmaf(r0.w, x, r3.x);
        float l4 = fmaf(r1.x, x, r3.y);
        float l5 = fmaf(r1.y, x, r3.z);
        float l6 = fmaf(r1.z, x, r3.w);
        float l7 = fmaf(r1.w, x, r4.x);
        float l8 = fmaf(r2.x, x, r4.y);

        // balanced max tree
        float m0 = fmaxf(l0, l1), m1 = fmaxf(l2, l3), m2 = fmaxf(l4, l5),
              m3 = fmaxf(l6, l7);
        float mx = fmaxf(fmaxf(fmaxf(m0, m1), fmaxf(m2, m3)), l8);

        float e0 = exp2f(l0 - mx), e1 = exp2f(l1 - mx), e2 = exp2f(l2 - mx);
        float e3 = exp2f(l3 - mx), e4 = exp2f(l4 - mx), e5 = exp2f(l5 - mx);
        float e6 = exp2f(l6 - mx), e7 = exp2f(l7 - mx), e8 = exp2f(l8 - mx);

        float s0 = e0 + e1, s1 = e2 + e3, s2 = e4 + e5, s3 = e6 + e7;
        float sum = ((s0 + s1) + (s2 + s3)) + e8;
        float inv = __fdividef(1.0f, sum);

        out[0] = 0.0f;
        out[1] = e0 * inv; out[2] = e1 * inv; out[3] = e2 * inv;
        out[4] = e3 * inv; out[5] = e4 * inv; out[6] = e5 * inv;
        out[7] = e6 * inv; out[8] = e7 * inv; out[9] = e8 * inv;
    } else {
        mask[e] = 0.0f;
        out[0] = 1.0f;
        #pragma unroll
        for (int k = 1; k < NBINS; k++) out[k] = 0.0f;
    }

    #pragma unroll
    for (int k = 0; k < NBINS; k++) sOut[t * NBINS + k] = out[k];
    __syncthreads();

    // Coalesced flush: 2560 floats = 640 float4 per block; base 16B-aligned
    float4* dst = reinterpret_cast<float4*>(probs + (size_t)blockIdx.x * (BLK * NBINS));
    const float4* src = reinterpret_cast<const float4*>(sOut);
    #pragma unroll
    for (int i = 0; i < 3; i++) {
        int idx = t + BLK * i;
        if (idx < (BLK * NBINS) / 4) dst[idx] = src[idx];
    }
}

extern "C" void kernel_launch(void* const* d_in, const int* in_sizes, int n_in,
                              void* d_out, int out_size) {
    const float* expr = (const float*)d_in[0];
    const float* W1   = (const float*)d_in[1];
    const float* b1   = (const float*)d_in[2];
    const float* W2   = (const float*)d_in[3];
    const float* b2   = (const float*)d_in[4];

    float* probs = (float*)d_out;
    float* mask  = (float*)d_out + (size_t)N_ELEM * NBINS;

    setup_kernel<<<1, NSEG * NBM1>>>(W1, b1, W2, b2);   // 585 threads >= 64,65
    expr_quantizer_kernel<<<NBLK, BLK>>>(expr, probs, mask);
}

// round 7
// speedup vs baseline: 1.6553x; 1.6006x over previous
#include <cuda_runtime.h>
#include <cstdint>

// Problem constants
#define B_DIM 128
#define G_DIM 20000
#define N_ELEM (B_DIM * G_DIM)   // 2,560,000 (divisible by 256)
#define HID 64
#define NBM1 9                   // NUM_BINS - 1
#define NBINS 10
#define NSEG (HID + 1)           // 65 piecewise-linear segments
#define ROWF 20                  // floats per table row (A0..A8,C0..C8,pad,pad) = 80B
#define BLK 256
#define NBLK (N_ELEM / BLK)      // 10,000
#define LOG2E 1.4426950408889634f

// __device__ global scratch (no allocations allowed)
__device__ float g_T[HID];                          // sorted thresholds
__device__ __align__(16) float g_tab[NSEG * ROWF];  // log2-domain (A', C') table

// ---------------------------------------------------------------------------
// Setup: build the piecewise-linear table (log2 domain), parallelized:
// grid = NSEG blocks (one segment each), 288 threads (9 warps; warp k
// reduces entry (j,k) over h with shuffles).
// logit_k(x) = b2[k] + sum_h W2[h,k] * leaky(x*w1[h] + b1[h]); the leaky
// sign pattern changes only at thr_h = -b1[h]/w1[h]. For segment j:
//   w1>0 : pre-act >= 0  <=>  rank(thr_h) < j
//   w1<0 : pre-act >= 0  <=>  rank(thr_h) >= j
//   w1==0: pre-act >= 0  <=>  b1 >= 0     (thr = +inf, excluded from search)
// ---------------------------------------------------------------------------
__global__ void setup_kernel(const float* __restrict__ W1,
                             const float* __restrict__ b1,
                             const float* __restrict__ W2,
                             const float* __restrict__ b2) {
    __shared__ float s_thr[HID];
    __shared__ int   s_rank[HID];
    __shared__ float s_w1[HID];
    __shared__ float s_b1[HID];

    int t = threadIdx.x;
    if (t < HID) {
        float w = W1[t];
        float b = b1[t];
        s_w1[t] = w;
        s_b1[t] = b;
        s_thr[t] = (w != 0.0f) ? (-b / w) : __int_as_float(0x7f800000); // +inf
    }
    __syncthreads();

    if (t < HID) {
        float thr = s_thr[t];
        int idx = 0;
        #pragma unroll
        for (int h = 0; h < HID; h++) {
            float o = s_thr[h];
            if (o < thr || (o == thr && h < t)) idx++;  // stable rank
        }
        s_rank[t] = idx;
        if (blockIdx.x == 0) g_T[idx] = thr;  // only one block writes g_T
    }
    __syncthreads();

    int j    = blockIdx.x;       // segment
    int k    = t >> 5;           // warp id = bin
    int lane = t & 31;
    if (k < NBM1) {
        float A = 0.0f, C = 0.0f;
        #pragma unroll
        for (int hh = 0; hh < 2; hh++) {
            int h = lane + 32 * hh;
            float w = s_w1[h];
            float b = s_b1[h];
            bool pos;
            if (w > 0.0f)      pos = (s_rank[h] < j);
            else if (w < 0.0f) pos = (s_rank[h] >= j);
            else               pos = (b >= 0.0f);
            float scale = pos ? 1.0f : 0.01f;
            float w2s = W2[h * NBM1 + k] * scale;
            A = fmaf(w2s, w, A);
            C = fmaf(w2s, b, C);
        }
        #pragma unroll
        for (int off = 16; off > 0; off >>= 1) {
            A += __shfl_down_sync(0xffffffffu, A, off);
            C += __shfl_down_sync(0xffffffffu, C, off);
        }
        if (lane == 0) {
            g_tab[j * ROWF + k]        = A * LOG2E;
            g_tab[j * ROWF + NBM1 + k] = (C + b2[k]) * LOG2E;
        }
    }
    if (t == 288 - 1) {  // zero row padding (float4 tail reads are harmless but be clean)
        g_tab[j * ROWF + 18] = 0.0f;
        g_tab[j * ROWF + 19] = 0.0f;
    }
}

// ---------------------------------------------------------------------------
// Main: sparsity-compacted. All threads do cheap zero-path work; nonzero
// elements (~10%) are compacted into a smem list and processed by the first
// n threads only (typically < 1 warp per block), reading table rows straight
// from global (L1-hot). Output assembled in smem, flushed as float4.
// ---------------------------------------------------------------------------
__global__ void __launch_bounds__(BLK)
expr_quantizer_kernel(const float* __restrict__ expr,
                      float* __restrict__ probs,
                      float* __restrict__ mask) {
    __shared__ __align__(16) float sOut[BLK * NBINS];  // 10 KB staging
    __shared__ float sT[HID];
    __shared__ float s_xv[BLK];
    __shared__ int   s_xi[BLK];
    __shared__ int   s_cnt;

    int t = threadIdx.x;
    if (t == 0) s_cnt = 0;
    if (t < HID) sT[t] = g_T[t];

    // Zero-prefill staging (640 float4s)
    {
        float4 z = make_float4(0.0f, 0.0f, 0.0f, 0.0f);
        float4* so4 = reinterpret_cast<float4*>(sOut);
        so4[t] = z;
        so4[t + BLK] = z;
        if (t < (BLK * NBINS) / 4 - 2 * BLK) so4[t + 2 * BLK] = z;
    }
    __syncthreads();

    int e = blockIdx.x * BLK + t;
    float x = __ldg(&expr[e]);
    bool nz = (x != 0.0f);
    mask[e] = nz ? 1.0f : 0.0f;
    sOut[t * NBINS] = nz ? 0.0f : 1.0f;   // bin-0 prob
    if (nz) {
        int p = atomicAdd(&s_cnt, 1);
        s_xv[p] = x;
        s_xi[p] = t;
    }
    __syncthreads();

    int n = s_cnt;
    if (t < n) {
        float xx = s_xv[t];
        int idx = s_xi[t];

        // j = count of sorted thresholds <= xx, in [0, 64]
        int j = 0;
        #pragma unroll
        for (int step = 64; step > 0; step >>= 1) {
            int nj = j + step;
            if (nj <= HID && sT[nj - 1] <= xx) j = nj;
        }

        const float4* row = reinterpret_cast<const float4*>(g_tab + j * ROWF);
        float4 r0 = __ldg(row + 0);  // A0..A3
        float4 r1 = __ldg(row + 1);  // A4..A7
        float4 r2 = __ldg(row + 2);  // A8, C0, C1, C2
        float4 r3 = __ldg(row + 3);  // C3..C6
        float4 r4 = __ldg(row + 4);  // C7, C8, pad, pad

        float l0 = fmaf(r0.x, xx, r2.y);
        float l1 = fmaf(r0.y, xx, r2.z);
        float l2 = fmaf(r0.z, xx, r2.w);
        float l3 = fmaf(r0.w, xx, r3.x);
        float l4 = fmaf(r1.x, xx, r3.y);
        float l5 = fmaf(r1.y, xx, r3.z);
        float l6 = fmaf(r1.z, xx, r3.w);
        float l7 = fmaf(r1.w, xx, r4.x);
        float l8 = fmaf(r2.x, xx, r4.y);

        float m0 = fmaxf(l0, l1), m1 = fmaxf(l2, l3);
        float m2 = fmaxf(l4, l5), m3 = fmaxf(l6, l7);
        float mx = fmaxf(fmaxf(fmaxf(m0, m1), fmaxf(m2, m3)), l8);

        float e0 = exp2f(l0 - mx), e1 = exp2f(l1 - mx), e2 = exp2f(l2 - mx);
        float e3 = exp2f(l3 - mx), e4 = exp2f(l4 - mx), e5 = exp2f(l5 - mx);
        float e6 = exp2f(l6 - mx), e7 = exp2f(l7 - mx), e8 = exp2f(l8 - mx);

        float s0 = e0 + e1, s1 = e2 + e3, s2 = e4 + e5, s3 = e6 + e7;
        float sum = ((s0 + s1) + (s2 + s3)) + e8;
        float inv = __fdividef(1.0f, sum);

        float* o = &sOut[idx * NBINS];
        o[1] = e0 * inv; o[2] = e1 * inv; o[3] = e2 * inv;
        o[4] = e3 * inv; o[5] = e4 * inv; o[6] = e5 * inv;
        o[7] = e6 * inv; o[8] = e7 * inv; o[9] = e8 * inv;
    }
    __syncthreads();

    // Coalesced flush: 2560 floats = 640 float4 per block; base 16B-aligned
    float4* dst = reinterpret_cast<float4*>(probs + (size_t)blockIdx.x * (BLK * NBINS));
    const float4* src = reinterpret_cast<const float4*>(sOut);
    dst[t] = src[t];
    dst[t + BLK] = src[t + BLK];
    if (t < (BLK * NBINS) / 4 - 2 * BLK) dst[t + 2 * BLK] = src[t + 2 * BLK];
}

extern "C" void kernel_launch(void* const* d_in, const int* in_sizes, int n_in,
                              void* d_out, int out_size) {
    const float* expr = (const float*)d_in[0];
    const float* W1   = (const float*)d_in[1];
    const float* b1   = (const float*)d_in[2];
    const float* W2   = (const float*)d_in[3];
    const float* b2   = (const float*)d_in[4];

    float* probs = (float*)d_out;
    float* mask  = (float*)d_out + (size_t)N_ELEM * NBINS;

    setup_kernel<<<NSEG, 288>>>(W1, b1, W2, b2);
    expr_quantizer_kernel<<<NBLK, BLK>>>(expr, probs, mask);
}

// round 8
// speedup vs baseline: 1.8848x; 1.1387x over previous
#include <cuda_runtime.h>
#include <cstdint>

// Problem constants
#define B_DIM 128
#define G_DIM 20000
#define N_ELEM (B_DIM * G_DIM)   // 2,560,000 (divisible by 256)
#define HID 64
#define NBM1 9                   // NUM_BINS - 1
#define NBINS 10
#define NSEG (HID + 1)           // 65 piecewise-linear segments
#define ROWF 20                  // floats per table row (A0..A8,C0..C8,pad,pad) = 80B
#define BLK 256
#define NBLK (N_ELEM / BLK)      // 10,000
#define LOG2E 1.4426950408889634f

// __device__ global scratch (no allocations allowed)
__device__ float g_T[HID];                          // sorted thresholds
__device__ __align__(16) float g_tab[NSEG * ROWF];  // log2-domain (A', C') table

// ---------------------------------------------------------------------------
// Setup: build the piecewise-linear table (log2 domain), parallelized:
// grid = NSEG blocks (one segment each), 288 threads (9 warps; warp k
// reduces entry (j,k) over h with shuffles).
// logit_k(x) = b2[k] + sum_h W2[h,k] * leaky(x*w1[h] + b1[h]); the leaky
// sign pattern changes only at thr_h = -b1[h]/w1[h]. For segment j:
//   w1>0 : pre-act >= 0  <=>  rank(thr_h) < j
//   w1<0 : pre-act >= 0  <=>  rank(thr_h) >= j
//   w1==0: pre-act >= 0  <=>  b1 >= 0     (thr = +inf, excluded from search)
// ---------------------------------------------------------------------------
__global__ void setup_kernel(const float* __restrict__ W1,
                             const float* __restrict__ b1,
                             const float* __restrict__ W2,
                             const float* __restrict__ b2) {
    __shared__ float s_thr[HID];
    __shared__ int   s_rank[HID];
    __shared__ float s_w1[HID];
    __shared__ float s_b1[HID];

    int t = threadIdx.x;
    if (t < HID) {
        float w = W1[t];
        float b = b1[t];
        s_w1[t] = w;
        s_b1[t] = b;
        s_thr[t] = (w != 0.0f) ? (-b / w) : __int_as_float(0x7f800000); // +inf
    }
    __syncthreads();

    if (t < HID) {
        float thr = s_thr[t];
        int idx = 0;
        #pragma unroll
        for (int h = 0; h < HID; h++) {
            float o = s_thr[h];
            if (o < thr || (o == thr && h < t)) idx++;  // stable rank
        }
        s_rank[t] = idx;
        if (blockIdx.x == 0) g_T[idx] = thr;  // only one block writes g_T
    }
    __syncthreads();

    int j    = blockIdx.x;       // segment
    int k    = t >> 5;           // warp id = bin
    int lane = t & 31;
    if (k < NBM1) {
        float A = 0.0f, C = 0.0f;
        #pragma unroll
        for (int hh = 0; hh < 2; hh++) {
            int h = lane + 32 * hh;
            float w = s_w1[h];
            float b = s_b1[h];
            bool pos;
            if (w > 0.0f)      pos = (s_rank[h] < j);
            else if (w < 0.0f) pos = (s_rank[h] >= j);
            else               pos = (b >= 0.0f);
            float scale = pos ? 1.0f : 0.01f;
            float w2s = W2[h * NBM1 + k] * scale;
            A = fmaf(w2s, w, A);
            C = fmaf(w2s, b, C);
        }
        #pragma unroll
        for (int off = 16; off > 0; off >>= 1) {
            A += __shfl_down_sync(0xffffffffu, A, off);
            C += __shfl_down_sync(0xffffffffu, C, off);
        }
        if (lane == 0) {
            g_tab[j * ROWF + k]        = A * LOG2E;
            g_tab[j * ROWF + NBM1 + k] = (C + b2[k]) * LOG2E;
        }
    }
    if (t == 288 - 1) {  // zero row padding
        g_tab[j * ROWF + 18] = 0.0f;
        g_tab[j * ROWF + 19] = 0.0f;
    }
}

// ---------------------------------------------------------------------------
// Main: sparsity-compacted compute + TMA bulk-store flush.
// All threads do cheap zero-path work; nonzero elements (~10%) are compacted
// into a smem list and processed by the first n threads only. The 10 KB
// staging buffer is flushed with ONE cp.async.bulk (shared->global) so the
// flush bypasses the SM's LSU/L1 path entirely (async proxy).
// ---------------------------------------------------------------------------
__global__ void __launch_bounds__(BLK)
expr_quantizer_kernel(const float* __restrict__ expr,
                      float* __restrict__ probs,
                      float* __restrict__ mask) {
    __shared__ __align__(16) float sOut[BLK * NBINS];  // 10 KB staging
    __shared__ float sT[HID];
    __shared__ float s_xv[BLK];
    __shared__ int   s_xi[BLK];
    __shared__ int   s_cnt;

    int t = threadIdx.x;
    if (t == 0) s_cnt = 0;
    if (t < HID) sT[t] = g_T[t];

    // Zero-prefill staging (640 float4s)
    {
        float4 z = make_float4(0.0f, 0.0f, 0.0f, 0.0f);
        float4* so4 = reinterpret_cast<float4*>(sOut);
        so4[t] = z;
        so4[t + BLK] = z;
        if (t < (BLK * NBINS) / 4 - 2 * BLK) so4[t + 2 * BLK] = z;
    }
    __syncthreads();

    int e = blockIdx.x * BLK + t;
    float x = __ldg(&expr[e]);
    bool nz = (x != 0.0f);
    mask[e] = nz ? 1.0f : 0.0f;
    sOut[t * NBINS] = nz ? 0.0f : 1.0f;   // bin-0 prob
    if (nz) {
        int p = atomicAdd(&s_cnt, 1);
        s_xv[p] = x;
        s_xi[p] = t;
    }
    __syncthreads();

    int n = s_cnt;
    if (t < n) {
        float xx = s_xv[t];
        int idx = s_xi[t];

        // j = count of sorted thresholds <= xx, in [0, 64]
        int j = 0;
        #pragma unroll
        for (int step = 64; step > 0; step >>= 1) {
            int nj = j + step;
            if (nj <= HID && sT[nj - 1] <= xx) j = nj;
        }

        const float4* row = reinterpret_cast<const float4*>(g_tab + j * ROWF);
        float4 r0 = __ldg(row + 0);  // A0..A3
        float4 r1 = __ldg(row + 1);  // A4..A7
        float4 r2 = __ldg(row + 2);  // A8, C0, C1, C2
        float4 r3 = __ldg(row + 3);  // C3..C6
        float4 r4 = __ldg(row + 4);  // C7, C8, pad, pad

        float l0 = fmaf(r0.x, xx, r2.y);
        float l1 = fmaf(r0.y, xx, r2.z);
        float l2 = fmaf(r0.z, xx, r2.w);
        float l3 = fmaf(r0.w, xx, r3.x);
        float l4 = fmaf(r1.x, xx, r3.y);
        float l5 = fmaf(r1.y, xx, r3.z);
        float l6 = fmaf(r1.z, xx, r3.w);
        float l7 = fmaf(r1.w, xx, r4.x);
        float l8 = fmaf(r2.x, xx, r4.y);

        float m0 = fmaxf(l0, l1), m1 = fmaxf(l2, l3);
        float m2 = fmaxf(l4, l5), m3 = fmaxf(l6, l7);
        float mx = fmaxf(fmaxf(fmaxf(m0, m1), fmaxf(m2, m3)), l8);

        float e0 = exp2f(l0 - mx), e1 = exp2f(l1 - mx), e2 = exp2f(l2 - mx);
        float e3 = exp2f(l3 - mx), e4 = exp2f(l4 - mx), e5 = exp2f(l5 - mx);
        float e6 = exp2f(l6 - mx), e7 = exp2f(l7 - mx), e8 = exp2f(l8 - mx);

        float s0 = e0 + e1, s1 = e2 + e3, s2 = e4 + e5, s3 = e6 + e7;
        float sum = ((s0 + s1) + (s2 + s3)) + e8;
        float inv = __fdividef(1.0f, sum);

        float* o = &sOut[idx * NBINS];
        o[1] = e0 * inv; o[2] = e1 * inv; o[3] = e2 * inv;
        o[4] = e3 * inv; o[5] = e4 * inv; o[6] = e5 * inv;
        o[7] = e6 * inv; o[8] = e7 * inv; o[9] = e8 * inv;
    }
    __syncthreads();

    // TMA bulk-store flush: 10240B contiguous, 16B-aligned both sides.
    // Bypasses LSU/L1 — the async proxy reads smem and writes L2 directly.
    if (t == 0) {
        asm volatile("fence.proxy.async.shared::cta;" ::: "memory");
        uint32_t ssrc = (uint32_t)__cvta_generic_to_shared(sOut);
        void* gdst = (void*)(probs + (size_t)blockIdx.x * (BLK * NBINS));
        asm volatile(
            "cp.async.bulk.global.shared::cta.bulk_group [%0], [%1], %2;"
            :: "l"(gdst), "r"(ssrc), "n"(BLK * NBINS * 4) : "memory");
        asm volatile("cp.async.bulk.commit_group;" ::: "memory");
        // smem must stay alive until the bulk read completes
        asm volatile("cp.async.bulk.wait_group.read 0;" ::: "memory");
    }
}

extern "C" void kernel_launch(void* const* d_in, const int* in_sizes, int n_in,
                              void* d_out, int out_size) {
    const float* expr = (const float*)d_in[0];
    const float* W1   = (const float*)d_in[1];
    const float* b1   = (const float*)d_in[2];
    const float* W2   = (const float*)d_in[3];
    const float* b2   = (const float*)d_in[4];

    float* probs = (float*)d_out;
    float* mask  = (float*)d_out + (size_t)N_ELEM * NBINS;

    setup_kernel<<<NSEG, 288>>>(W1, b1, W2, b2);
    expr_quantizer_kernel<<<NBLK, BLK>>>(expr, probs, mask);
}